// round 14
// baseline (speedup 1.0000x reference)
#include <cuda_runtime.h>
#include <cstdint>

#define BATCH 4
#define CCH 7
#define DD 32
#define HH 192
#define WW 192
#define DHW (DD*HH*WW)        // 1179648
#define NIDS 16
#define NSEG (BATCH*NIDS)     // 64
#define NBITS 13
#define NB (1<<NBITS)         // 8192 bins over e in [0,2]
#define NCH 64                // chunks per segment
#define CHUNK (NB/NCH)        // 128 bins per chunk
#define ROUNDS (CHUNK/32)     // 4 warp rounds per chunk

typedef unsigned long long u64;

// ---------------- device scratch (static; BSS zero-init at load) ----------------
__device__ double g_stats[NSEG][8];              // cnt,Sx,Sy,Sz,Ss0..2,Sq (zeroed by stats last block)
__device__ double g_bg[BATCH];                   // bg seed loss (zeroed by scan last block)
__device__ double g_seedl[NSEG];                 // fg seed loss (zeroed by scan last block)
__device__ double g_instl[NSEG];                 // lovasz accum (zeroed by scan last block)
__device__ float g_params[NSEG][8];              // cx,cy,cz, ex,ey,ez, cnt, var
__device__ u64 g_hist[(size_t)NSEG*NB];          // 4MB (self-zeroed by scan pass 2)
__device__ u64 g_csum[NSEG][NCH];                // per-chunk packed sums (overwritten each run)
__device__ unsigned g_ctr1;                      // stats retirement counter (self-reset)
__device__ unsigned g_ctr2;                      // scan retirement counter (self-reset)

// ---------------- K1: per-instance stats + fused finalize (last-block) ----------------
// Each warp's 32 voxels sit in ONE row (32 | 192): hi,di warp-uniform, wi = w0+lane.
// Integer stats (cnt, sum wi, sum hi, sum di) are EXACT via popc arithmetic, no atomics.
// Sigma sums: f32 smem atomics into 2 slots per (warp,id) selected by lane parity.
__global__ __launch_bounds__(1024) void stats_kernel(const float* __restrict__ pred,
                                                     const int* __restrict__ inst) {
    __shared__ int   s_int[32*16*4];             // 8KB: one write per (warp,id), no atomics
    __shared__ float s_flt[32*16*10];            // 20KB: [warp][id][slot(2)][stat(4)+pad]
    __shared__ bool  s_last;
    int tid = threadIdx.x;
    int lane = tid & 31, wid = tid >> 5;
    for (int i = tid; i < 32*16*4; i += 1024) s_int[i] = 0;
    for (int i = tid; i < 32*16*10; i += 1024) s_flt[i] = 0.f;
    __syncthreads();

    const int bpb = DHW/1024;                    // 1152 blocks per batch (exact)
    int b = blockIdx.x / bpb;
    int v = (blockIdx.x % bpb)*1024 + tid;

    int warpbase = v & ~31;
    int w0 = warpbase % WW;                      // warp-uniform
    int t2 = warpbase / WW;
    int hi = t2 % HH;                            // warp-uniform
    int di = t2 / HH;                            // warp-uniform

    size_t pbase = (size_t)b*CCH*DHW + v;
    float s0 = pred[pbase + 3*(size_t)DHW];
    float s1 = pred[pbase + 4*(size_t)DHW];
    float s2 = pred[pbase + 5*(size_t)DHW];
    int iv = inst[(size_t)b*DHW + v];

    // one ballot per id; lane i keeps mask for id i
    unsigned mymask = 0;
    #pragma unroll
    for (int id = 0; id < NIDS; id++) {
        unsigned m = __ballot_sync(0xffffffffu, iv == id+1);
        if (lane == id) mymask = m;
    }
    if (lane < NIDS && mymask) {
        int cnt = __popc(mymask);
        int sl  = __popc(mymask & 0xFFFF0000u)*16
                + __popc(mymask & 0xFF00FF00u)*8
                + __popc(mymask & 0xF0F0F0F0u)*4
                + __popc(mymask & 0xCCCCCCCCu)*2
                + __popc(mymask & 0xAAAAAAAAu);   // sum of set lane indices
        int* si = &s_int[(wid*16 + lane)*4];
        si[0] = cnt;
        si[1] = w0*cnt + sl;                     // sum wi
        si[2] = hi*cnt;                          // sum hi
        si[3] = di*cnt;                          // sum di
    }
    if (iv >= 1 && iv <= NIDS) {
        float* a = &s_flt[(wid*16 + (iv-1))*10 + (lane & 1)*5];
        atomicAdd(&a[0], s0);
        atomicAdd(&a[1], s1);
        atomicAdd(&a[2], s2);
        atomicAdd(&a[3], s0*s0 + s1*s1 + s2*s2);
    }
    __syncthreads();

    // flush: 128 threads = 16 ids x 8 stats (0=cnt,1=Sx,2=Sy,3=Sz,4..6=Ss,7=Sq)
    if (tid < 128) {
        int id = tid >> 3, k = tid & 7;
        double val = 0.0;
        if (k < 4) {
            long long acc = 0;
            #pragma unroll
            for (int w = 0; w < 32; w++) acc += (long long)s_int[(w*16 + id)*4 + k];
            if      (k == 0) val = (double)acc;
            else if (k == 3) val = (double)acc * (1.0/31.0);
            else             val = (double)acc * (1.0/191.0);
        } else {
            float f = 0.f;
            #pragma unroll
            for (int w = 0; w < 32; w++) {
                const float* a = &s_flt[(w*16 + id)*10];
                f += a[k-4] + a[5 + (k-4)];
            }
            val = (double)f;
        }
        if (val != 0.0) atomicAdd(&g_stats[b*NIDS + id][k], val);
    }

    // ---- last-block retirement: fused finalize ----
    __threadfence();
    __syncthreads();
    if (tid == 0) {
        unsigned old = atomicAdd(&g_ctr1, 1u);
        s_last = (old == gridDim.x - 1);
    }
    __syncthreads();
    if (s_last) {
        if (tid < NSEG) {
            int i = tid;
            double s[8];
            #pragma unroll
            for (int k = 0; k < 8; k++) {
                s[k] = __ldcg(&g_stats[i][k]);
                g_stats[i][k] = 0.0;             // self-zero for next replay
            }
            double cnt  = s[0];
            double safe = cnt > 1.0 ? cnt : 1.0;
            double inv  = 1.0/safe;
            double m0 = s[4]*inv, m1 = s[5]*inv, m2 = s[6]*inv;
            double varnum = s[7] - 2.0*(m0*s[4] + m1*s[5] + m2*s[6])
                          + (m0*m0 + m1*m1 + m2*m2)*cnt;
            g_params[i][0] = (float)(s[1]*inv);
            g_params[i][1] = (float)(s[2]*inv);
            g_params[i][2] = (float)(s[3]*inv);
            g_params[i][3] = expf(10.f*(float)m0);
            g_params[i][4] = expf(10.f*(float)m1);
            g_params[i][5] = expf(10.f*(float)m2);
            g_params[i][6] = (float)cnt;
            g_params[i][7] = (float)(varnum/(3.0*safe));
        }
        if (tid == 0) g_ctr1 = 0;                // reset for next replay
    }
}

// ---------------- K3: fused preprocess + dist + histogram + seed losses ----------------
__global__ __launch_bounds__(256) void hist_kernel(const float* __restrict__ pred,
                                                   const int* __restrict__ inst,
                                                   const int* __restrict__ lab) {
    __shared__ float s_p[NIDS*6];
    __shared__ float s_sl[NIDS];
    __shared__ float s_bg;
    int tid = threadIdx.x;
    int lane = tid & 31;
    const int bpb = DHW/256;
    int b = blockIdx.x / bpb;
    int v = (blockIdx.x % bpb)*256 + tid;
    if (tid < NIDS*6) s_p[tid] = g_params[b*NIDS + tid/6][tid%6];
    if (tid < NIDS) s_sl[tid] = 0.f;
    if (tid == 0) s_bg = 0.f;
    __syncthreads();

    int wi = v % WW;
    int t2 = v / WW;
    int hh = t2 % HH;
    int dd = t2 / HH;
    float x0 = (float)wi * (1.f/191.f);
    float x1 = (float)hh * (1.f/191.f);
    float x2 = (float)dd * (1.f/31.f);

    size_t pbase = (size_t)b*CCH*DHW + v;
    float p0 = pred[pbase];
    float p1 = pred[pbase + (size_t)DHW];
    float p2 = pred[pbase + 2*(size_t)DHW];
    float p6 = pred[pbase + 6*(size_t)DHW];
    int iv   = inst[(size_t)b*DHW + v];
    int lv   = lab[(size_t)b*DHW + v];

    float se0 = tanhf(p0) + x0;
    float se1 = tanhf(p1) + x1;
    float se2 = tanhf(p2) + x2;
    float sd  = 1.f/(1.f + __expf(-p6));

    // bg seed: warp reduce then one shared atomic per warp
    float bgv = (lv == 0) ? sd*sd : 0.f;
    #pragma unroll
    for (int off = 16; off; off >>= 1) bgv += __shfl_down_sync(0xffffffffu, bgv, off);
    if (lane == 0 && bgv != 0.f) atomicAdd(&s_bg, bgv);

    u64* hb = g_hist + (((size_t)b*NIDS) << NBITS);
    #pragma unroll
    for (int i = 0; i < NIDS; i++) {
        float d0 = se0 - s_p[i*6+0];
        float d1 = se1 - s_p[i*6+1];
        float d2 = se2 - s_p[i*6+2];
        float q  = d0*d0*s_p[i*6+3] + d1*d1*s_p[i*6+4] + d2*d2*s_p[i*6+5];
        float d  = __expf(-q);
        bool gt  = (iv == i+1);
        float e  = gt ? (2.f - 2.f*d) : (2.f*d);
        int bin  = (int)(e * (float)(NB/2));
        if (bin > NB-1) bin = NB-1;
        if (bin < 0) bin = 0;
        atomicAdd(&hb[((size_t)i << NBITS) + bin], gt ? (1ULL<<32) : 1ULL);
        if (gt) { float df = sd - d; atomicAdd(&s_sl[i], df*df); }
    }
    __syncthreads();
    if (tid < NIDS && s_sl[tid] != 0.f)
        atomicAdd(&g_seedl[b*NIDS + tid], (double)s_sl[tid]);
    if (tid == 0 && s_bg != 0.f) atomicAdd(&g_bg[b], (double)s_bg);
}

// ---------------- K4a: per-chunk packed sums (coalesced, chip-filling grid) ----------------
__global__ __launch_bounds__(256) void chunk_sum_kernel() {
    int lane = threadIdx.x & 31;
    int gw = blockIdx.x*8 + (threadIdx.x >> 5);  // global warp id, 4096 total
    int seg = gw >> 6;
    int ch  = gw & (NCH-1);
    const u64* hist = g_hist + ((size_t)seg << NBITS);
    int base = ch*CHUNK;                         // descending-position base
    u64 sum = 0;
    #pragma unroll
    for (int r = 0; r < ROUNDS; r++) {
        u64 hv = hist[NB-1 - (base + r*32 + lane)];
        sum += hv + (hv >> 32);
    }
    #pragma unroll
    for (int off = 16; off; off >>= 1)
        sum += __shfl_down_sync(0xffffffffu, sum, off);
    if (lane == 0) g_csum[seg][ch] = sum;
}

// ---------------- K4b: Lovasz main pass + fused final combine (last-block) ----------------
__global__ __launch_bounds__(256) void lovasz_scan_kernel(float* __restrict__ out) {
    __shared__ bool s_last;
    int tid = threadIdx.x;
    int lane = tid & 31;
    int gw = blockIdx.x*8 + (tid >> 5);
    int seg = gw >> 6;
    int ch  = gw & (NCH-1);
    u64* hist = g_hist + ((size_t)seg << NBITS);
    long long gts = (long long)(g_params[seg][6] + 0.5f);

    // inter-chunk exclusive prefix: sum csum of chunks [0, ch)
    u64 pre = 0;
    if (lane < ch) pre = g_csum[seg][lane];
    if (lane + 32 < ch) pre += g_csum[seg][lane + 32];
    #pragma unroll
    for (int off = 16; off; off >>= 1)
        pre += __shfl_xor_sync(0xffffffffu, pre, off);
    u64 carry = pre;                             // same in all lanes

    int base = ch*CHUNK;
    double acc = 0.0;
    const float width = 2.0f / (float)NB;

    #pragma unroll
    for (int r = 0; r < ROUNDS; r++) {
        int bin = NB-1 - (base + r*32 + lane);
        u64 hv = hist[bin];
        hist[bin] = 0ULL;                        // self-clean for next replay
        u64 pack = hv + (hv >> 32);

        // inclusive warp scan (ascending lane = descending bin order)
        u64 x = pack;
        #pragma unroll
        for (int off = 1; off < 32; off <<= 1) {
            u64 y = __shfl_up_sync(0xffffffffu, x, off);
            if (lane >= off) x += y;
        }
        u64 tot = __shfl_sync(0xffffffffu, x, 31);
        u64 run = carry + x - pack;              // exclusive prefix for this bin
        carry += tot;

        unsigned n1 = (unsigned)(hv >> 32);
        unsigned n0 = (unsigned)hv;
        if (n1 + n0) {
            long long n1b = (long long)(run >> 32);     // gt before this bin
            long long ntb = (long long)(unsigned)run;   // total before this bin
            long long interb = gts - n1b;
            long long unionb = gts + (ntb - n1b);
            long long intere = interb - (long long)n1;
            long long unione = unionb + (long long)n0;
            // Je - Jb = interb/unionb - intere/unione (exact int64 cross product)
            long long num = interb*unione - intere*unionb;
            long long den = unionb*unione;
            float e_rep = ((float)bin + 0.5f) * width;
            acc += (double)e_rep * ((double)num / (double)den);
        }
    }

    #pragma unroll
    for (int off = 16; off; off >>= 1)
        acc += __shfl_down_sync(0xffffffffu, acc, off);
    if (lane == 0 && gts > 0 && acc != 0.0)
        atomicAdd(&g_instl[seg], acc);

    // ---- last-block retirement: fused final combine ----
    __threadfence();
    __syncthreads();
    if (tid == 0) {
        unsigned old = atomicAdd(&g_ctr2, 1u);
        s_last = (old == gridDim.x - 1);
    }
    __syncthreads();
    if (s_last && tid == 0) {
        float li = 0.f, lv = 0.f, ls = 0.f;
        for (int b = 0; b < BATCH; b++) {
            float obj = 0.f, vb = 0.f, ib = 0.f, sb = 0.f;
            for (int i = 0; i < NIDS; i++) {
                int s = b*NIDS + i;
                float cnt = g_params[s][6];
                if (cnt > 0.f) {
                    obj += 1.f;
                    vb += g_params[s][7];
                    ib += (float)__ldcg(&g_instl[s]);
                    sb += (float)__ldcg(&g_seedl[s]);
                }
                g_seedl[s] = 0.0;
                g_instl[s] = 0.0;
            }
            float denom = obj > 1.f ? obj : 1.f;
            li += ib/denom;
            lv += vb/denom;
            ls += (sb + (float)__ldcg(&g_bg[b])) / (float)DHW;
            g_bg[b] = 0.0;
        }
        li = li * 1.0f / BATCH;          // W_INST
        lv = lv * 10.0f / BATCH;         // W_VAR
        ls = ls * 1.0f / BATCH;          // W_SEED
        out[0] = li; out[1] = lv; out[2] = ls; out[3] = li + lv + ls;
        g_ctr2 = 0;                      // reset for next replay
    }
}

// ---------------- launch ----------------
extern "C" void kernel_launch(void* const* d_in, const int* in_sizes, int n_in,
                              void* d_out, int out_size) {
    const float* pred = (const float*)d_in[0];
    const int*   inst = (const int*)d_in[1];
    const int*   lab  = (const int*)d_in[2];
    // d_in[3] = center_images (unused), d_in[4] = xyzm (grid; computed inline)
    float* out = (float*)d_out;

    stats_kernel<<<BATCH*(DHW/1024), 1024>>>(pred, inst);
    hist_kernel<<<BATCH*(DHW/256), 256>>>(pred, inst, lab);
    chunk_sum_kernel<<<(NSEG*NCH)/8, 256>>>();
    lovasz_scan_kernel<<<(NSEG*NCH)/8, 256>>>(out);
}

// round 15
// speedup vs baseline: 1.0552x; 1.0552x over previous
#include <cuda_runtime.h>
#include <cstdint>

#define BATCH 4
#define CCH 7
#define DD 32
#define HH 192
#define WW 192
#define DHW (DD*HH*WW)        // 1179648
#define NIDS 16
#define NSEG (BATCH*NIDS)     // 64
#define NBITS 13
#define NB (1<<NBITS)         // 8192 bins over e in [0,2]
#define NCH 64                // chunks per segment
#define CHUNK (NB/NCH)        // 128 bins per chunk
#define ROUNDS (CHUNK/32)     // 4 warp rounds per chunk

typedef unsigned long long u64;

// ---------------- device scratch (static; BSS zero-init at load) ----------------
__device__ double g_stats[NSEG][8];              // cnt,Sx,Sy,Sz,Ss0..2,Sq (self-zeroed by finalize)
__device__ double g_bg[BATCH];                   // bg seed loss (self-zeroed by final)
__device__ double g_seedl[NSEG];                 // fg seed loss (self-zeroed by final)
__device__ double g_instl[NSEG];                 // lovasz accum (self-zeroed by final)
__device__ float g_params[NSEG][8];              // cx,cy,cz, ex,ey,ez, cnt, var
__device__ u64 g_hist[(size_t)NSEG*NB];          // 4MB (self-zeroed by scan pass 2)
__device__ u64 g_csum[NSEG][NCH];                // per-chunk packed sums (overwritten each run)

// ---------------- K1: per-instance stats (ballot ints + 2-way-spread f32 smem atomics) ----------------
// Each warp's 32 voxels sit in ONE row (32 | 192): hi,di warp-uniform, wi = w0+lane.
// Integer stats (cnt, sum wi, sum hi, sum di) are EXACT via popc arithmetic, no atomics.
// Sigma sums: f32 smem atomics into 2 slots per (warp,id) selected by lane parity,
// halving the within-warp same-address replay chain.
__global__ __launch_bounds__(1024) void stats_kernel(const float* __restrict__ pred,
                                                     const int* __restrict__ inst) {
    __shared__ int   s_int[32*16*4];             // 8KB: one write per (warp,id), no atomics
    __shared__ float s_flt[32*16*10];            // 20KB: [warp][id][slot(2)][stat(4)+pad]
    int tid = threadIdx.x;
    int lane = tid & 31, wid = tid >> 5;
    for (int i = tid; i < 32*16*4; i += 1024) s_int[i] = 0;
    for (int i = tid; i < 32*16*10; i += 1024) s_flt[i] = 0.f;
    __syncthreads();

    const int bpb = DHW/1024;                    // 1152 blocks per batch (exact)
    int b = blockIdx.x / bpb;
    int v = (blockIdx.x % bpb)*1024 + tid;

    int warpbase = v & ~31;
    int w0 = warpbase % WW;                      // warp-uniform
    int t2 = warpbase / WW;
    int hi = t2 % HH;                            // warp-uniform
    int di = t2 / HH;                            // warp-uniform

    size_t pbase = (size_t)b*CCH*DHW + v;
    float s0 = pred[pbase + 3*(size_t)DHW];
    float s1 = pred[pbase + 4*(size_t)DHW];
    float s2 = pred[pbase + 5*(size_t)DHW];
    int iv = inst[(size_t)b*DHW + v];

    // one ballot per id; lane i keeps mask for id i
    unsigned mymask = 0;
    #pragma unroll
    for (int id = 0; id < NIDS; id++) {
        unsigned m = __ballot_sync(0xffffffffu, iv == id+1);
        if (lane == id) mymask = m;
    }
    if (lane < NIDS && mymask) {
        int cnt = __popc(mymask);
        int sl  = __popc(mymask & 0xFFFF0000u)*16
                + __popc(mymask & 0xFF00FF00u)*8
                + __popc(mymask & 0xF0F0F0F0u)*4
                + __popc(mymask & 0xCCCCCCCCu)*2
                + __popc(mymask & 0xAAAAAAAAu);   // sum of set lane indices
        int* si = &s_int[(wid*16 + lane)*4];
        si[0] = cnt;
        si[1] = w0*cnt + sl;                     // sum wi
        si[2] = hi*cnt;                          // sum hi
        si[3] = di*cnt;                          // sum di
    }
    if (iv >= 1 && iv <= NIDS) {
        float* a = &s_flt[(wid*16 + (iv-1))*10 + (lane & 1)*5];
        atomicAdd(&a[0], s0);
        atomicAdd(&a[1], s1);
        atomicAdd(&a[2], s2);
        atomicAdd(&a[3], s0*s0 + s1*s1 + s2*s2);
    }
    __syncthreads();

    // flush: 128 threads = 16 ids x 8 stats (0=cnt,1=Sx,2=Sy,3=Sz,4..6=Ss,7=Sq)
    if (tid < 128) {
        int id = tid >> 3, k = tid & 7;
        double val = 0.0;
        if (k < 4) {
            long long acc = 0;
            #pragma unroll
            for (int w = 0; w < 32; w++) acc += (long long)s_int[(w*16 + id)*4 + k];
            if      (k == 0) val = (double)acc;
            else if (k == 3) val = (double)acc * (1.0/31.0);
            else             val = (double)acc * (1.0/191.0);
        } else {
            float f = 0.f;
            #pragma unroll
            for (int w = 0; w < 32; w++) {
                const float* a = &s_flt[(w*16 + id)*10];
                f += a[k-4] + a[5 + (k-4)];
            }
            val = (double)f;
        }
        if (val != 0.0) atomicAdd(&g_stats[b*NIDS + id][k], val);
    }
}

// ---------------- K2: finalize per-instance params (+ self-zero stats) ----------------
__global__ void finalize_stats_kernel() {
    int i = threadIdx.x;
    if (i >= NSEG) return;
    double s[8];
    #pragma unroll
    for (int k = 0; k < 8; k++) { s[k] = g_stats[i][k]; g_stats[i][k] = 0.0; }
    double cnt  = s[0];
    double safe = cnt > 1.0 ? cnt : 1.0;
    double inv  = 1.0/safe;
    double c0 = s[1]*inv, c1 = s[2]*inv, c2 = s[3]*inv;
    double m0 = s[4]*inv, m1 = s[5]*inv, m2 = s[6]*inv;
    double varnum = s[7] - 2.0*(m0*s[4] + m1*s[5] + m2*s[6])
                  + (m0*m0 + m1*m1 + m2*m2)*cnt;
    double var = varnum/(3.0*safe);
    g_params[i][0] = (float)c0;
    g_params[i][1] = (float)c1;
    g_params[i][2] = (float)c2;
    g_params[i][3] = expf(10.f*(float)m0);
    g_params[i][4] = expf(10.f*(float)m1);
    g_params[i][5] = expf(10.f*(float)m2);
    g_params[i][6] = (float)cnt;
    g_params[i][7] = (float)var;
}

// ---------------- K3: fused preprocess + dist + histogram + seed losses ----------------
__global__ __launch_bounds__(256) void hist_kernel(const float* __restrict__ pred,
                                                   const int* __restrict__ inst,
                                                   const int* __restrict__ lab) {
    __shared__ float s_p[NIDS*6];
    __shared__ float s_sl[NIDS];
    __shared__ float s_bg;
    int tid = threadIdx.x;
    int lane = tid & 31;
    const int bpb = DHW/256;
    int b = blockIdx.x / bpb;
    int v = (blockIdx.x % bpb)*256 + tid;
    if (tid < NIDS*6) s_p[tid] = g_params[b*NIDS + tid/6][tid%6];
    if (tid < NIDS) s_sl[tid] = 0.f;
    if (tid == 0) s_bg = 0.f;
    __syncthreads();

    int wi = v % WW;
    int t2 = v / WW;
    int hh = t2 % HH;
    int dd = t2 / HH;
    float x0 = (float)wi * (1.f/191.f);
    float x1 = (float)hh * (1.f/191.f);
    float x2 = (float)dd * (1.f/31.f);

    size_t pbase = (size_t)b*CCH*DHW + v;
    float p0 = pred[pbase];
    float p1 = pred[pbase + (size_t)DHW];
    float p2 = pred[pbase + 2*(size_t)DHW];
    float p6 = pred[pbase + 6*(size_t)DHW];
    int iv   = inst[(size_t)b*DHW + v];
    int lv   = lab[(size_t)b*DHW + v];

    float se0 = tanhf(p0) + x0;
    float se1 = tanhf(p1) + x1;
    float se2 = tanhf(p2) + x2;
    float sd  = 1.f/(1.f + __expf(-p6));

    // bg seed: warp reduce then one shared atomic per warp
    float bgv = (lv == 0) ? sd*sd : 0.f;
    #pragma unroll
    for (int off = 16; off; off >>= 1) bgv += __shfl_down_sync(0xffffffffu, bgv, off);
    if (lane == 0 && bgv != 0.f) atomicAdd(&s_bg, bgv);

    u64* hb = g_hist + (((size_t)b*NIDS) << NBITS);
    #pragma unroll
    for (int i = 0; i < NIDS; i++) {
        float d0 = se0 - s_p[i*6+0];
        float d1 = se1 - s_p[i*6+1];
        float d2 = se2 - s_p[i*6+2];
        float q  = d0*d0*s_p[i*6+3] + d1*d1*s_p[i*6+4] + d2*d2*s_p[i*6+5];
        float d  = __expf(-q);
        bool gt  = (iv == i+1);
        float e  = gt ? (2.f - 2.f*d) : (2.f*d);
        int bin  = (int)(e * (float)(NB/2));
        if (bin > NB-1) bin = NB-1;
        if (bin < 0) bin = 0;
        atomicAdd(&hb[((size_t)i << NBITS) + bin], gt ? (1ULL<<32) : 1ULL);
        if (gt) { float df = sd - d; atomicAdd(&s_sl[i], df*df); }
    }
    __syncthreads();
    if (tid < NIDS && s_sl[tid] != 0.f)
        atomicAdd(&g_seedl[b*NIDS + tid], (double)s_sl[tid]);
    if (tid == 0 && s_bg != 0.f) atomicAdd(&g_bg[b], (double)s_bg);
}

// ---------------- K4a: per-chunk packed sums (coalesced, chip-filling grid) ----------------
__global__ __launch_bounds__(256) void chunk_sum_kernel() {
    int lane = threadIdx.x & 31;
    int gw = blockIdx.x*8 + (threadIdx.x >> 5);  // global warp id, 4096 total
    int seg = gw >> 6;
    int ch  = gw & (NCH-1);
    const u64* hist = g_hist + ((size_t)seg << NBITS);
    int base = ch*CHUNK;                         // descending-position base
    u64 sum = 0;
    #pragma unroll
    for (int r = 0; r < ROUNDS; r++) {
        u64 hv = hist[NB-1 - (base + r*32 + lane)];
        sum += hv + (hv >> 32);
    }
    #pragma unroll
    for (int off = 16; off; off >>= 1)
        sum += __shfl_down_sync(0xffffffffu, sum, off);
    if (lane == 0) g_csum[seg][ch] = sum;
}

// ---------------- K4b: Lovasz main pass (coalesced, self-zeroes hist) ----------------
__global__ __launch_bounds__(256) void lovasz_scan_kernel() {
    int lane = threadIdx.x & 31;
    int gw = blockIdx.x*8 + (threadIdx.x >> 5);
    int seg = gw >> 6;
    int ch  = gw & (NCH-1);
    u64* hist = g_hist + ((size_t)seg << NBITS);
    long long gts = (long long)(g_params[seg][6] + 0.5f);

    // inter-chunk exclusive prefix: sum csum of chunks [0, ch)
    u64 pre = 0;
    if (lane < ch) pre = g_csum[seg][lane];
    if (lane + 32 < ch) pre += g_csum[seg][lane + 32];
    #pragma unroll
    for (int off = 16; off; off >>= 1)
        pre += __shfl_xor_sync(0xffffffffu, pre, off);
    u64 carry = pre;                             // same in all lanes

    int base = ch*CHUNK;
    double acc = 0.0;
    const float width = 2.0f / (float)NB;

    #pragma unroll
    for (int r = 0; r < ROUNDS; r++) {
        int bin = NB-1 - (base + r*32 + lane);
        u64 hv = hist[bin];
        hist[bin] = 0ULL;                        // self-clean for next replay
        u64 pack = hv + (hv >> 32);

        // inclusive warp scan (ascending lane = descending bin order)
        u64 x = pack;
        #pragma unroll
        for (int off = 1; off < 32; off <<= 1) {
            u64 y = __shfl_up_sync(0xffffffffu, x, off);
            if (lane >= off) x += y;
        }
        u64 tot = __shfl_sync(0xffffffffu, x, 31);
        u64 run = carry + x - pack;              // exclusive prefix for this bin
        carry += tot;

        unsigned n1 = (unsigned)(hv >> 32);
        unsigned n0 = (unsigned)hv;
        if (n1 + n0) {
            long long n1b = (long long)(run >> 32);     // gt before this bin
            long long ntb = (long long)(unsigned)run;   // total before this bin
            long long interb = gts - n1b;
            long long unionb = gts + (ntb - n1b);
            long long intere = interb - (long long)n1;
            long long unione = unionb + (long long)n0;
            // Je - Jb = interb/unionb - intere/unione (exact int64 cross product)
            long long num = interb*unione - intere*unionb;
            long long den = unionb*unione;
            float e_rep = ((float)bin + 0.5f) * width;
            acc += (double)e_rep * ((double)num / (double)den);
        }
    }

    #pragma unroll
    for (int off = 16; off; off >>= 1)
        acc += __shfl_down_sync(0xffffffffu, acc, off);
    if (lane == 0 && gts > 0 && acc != 0.0)
        atomicAdd(&g_instl[seg], acc);
}

// ---------------- K5: final combine (+ self-zero accumulators) ----------------
__global__ void final_kernel(float* __restrict__ out) {
    if (threadIdx.x != 0) return;
    float li = 0.f, lv = 0.f, ls = 0.f;
    for (int b = 0; b < BATCH; b++) {
        float obj = 0.f, vb = 0.f, ib = 0.f, sb = 0.f;
        for (int i = 0; i < NIDS; i++) {
            int s = b*NIDS + i;
            float cnt = g_params[s][6];
            if (cnt > 0.f) {
                obj += 1.f;
                vb += g_params[s][7];
                ib += (float)g_instl[s];
                sb += (float)g_seedl[s];
            }
            g_seedl[s] = 0.0;
            g_instl[s] = 0.0;
        }
        float denom = obj > 1.f ? obj : 1.f;
        li += ib/denom;
        lv += vb/denom;
        ls += (sb + (float)g_bg[b]) / (float)DHW;
        g_bg[b] = 0.0;
    }
    li = li * 1.0f / BATCH;          // W_INST
    lv = lv * 10.0f / BATCH;         // W_VAR
    ls = ls * 1.0f / BATCH;          // W_SEED
    out[0] = li; out[1] = lv; out[2] = ls; out[3] = li + lv + ls;
}

// ---------------- launch ----------------
extern "C" void kernel_launch(void* const* d_in, const int* in_sizes, int n_in,
                              void* d_out, int out_size) {
    const float* pred = (const float*)d_in[0];
    const int*   inst = (const int*)d_in[1];
    const int*   lab  = (const int*)d_in[2];
    // d_in[3] = center_images (unused), d_in[4] = xyzm (grid; computed inline)
    float* out = (float*)d_out;

    stats_kernel<<<BATCH*(DHW/1024), 1024>>>(pred, inst);
    finalize_stats_kernel<<<1, 64>>>();
    hist_kernel<<<BATCH*(DHW/256), 256>>>(pred, inst, lab);
    chunk_sum_kernel<<<(NSEG*NCH)/8, 256>>>();
    lovasz_scan_kernel<<<(NSEG*NCH)/8, 256>>>();
    final_kernel<<<1, 32>>>(out);
}

// round 16
// speedup vs baseline: 1.1235x; 1.0647x over previous
#include <cuda_runtime.h>
#include <cstdint>

#define BATCH 4
#define CCH 7
#define DD 32
#define HH 192
#define WW 192
#define DHW (DD*HH*WW)        // 1179648
#define NIDS 16
#define NSEG (BATCH*NIDS)     // 64
#define NBITS 15
#define NB (1<<NBITS)         // 32768 bins over e in [0,2]
#define NCH 64                // chunks per segment
#define CHUNK (NB/NCH)        // 512 bins per chunk
#define ROUNDS (CHUNK/32)     // 16 warp rounds per chunk

typedef unsigned long long u64;

// ---------------- device scratch (static; BSS zero-init at load) ----------------
__device__ double g_stats[NSEG][8];              // cnt,Sx,Sy,Sz,Ss0..2,Sq (self-zeroed by finalize)
__device__ double g_bg[BATCH];                   // bg seed loss (self-zeroed by final)
__device__ double g_seedl[NSEG];                 // fg seed loss (self-zeroed by final)
__device__ double g_instl[NSEG];                 // lovasz accum (self-zeroed by final)
__device__ float g_params[NSEG][8];              // cx,cy,cz, ex,ey,ez, cnt, var
__device__ u64 g_hist[(size_t)NSEG*NB];          // 16MB (self-zeroed by scan pass 2)
__device__ u64 g_csum[NSEG][NCH];                // per-chunk packed sums (overwritten each run)

// ---------------- K1: per-instance stats (ballot ints + 2-way-spread f32 smem atomics) ----------------
// Each warp's 32 voxels sit in ONE row (32 | 192): hi,di warp-uniform, wi = w0+lane.
// Integer stats (cnt, sum wi, sum hi, sum di) are EXACT via popc arithmetic, no atomics.
// Sigma sums: f32 smem atomics into 2 slots per (warp,id) selected by lane parity,
// halving the within-warp same-address replay chain.
__global__ __launch_bounds__(1024) void stats_kernel(const float* __restrict__ pred,
                                                     const int* __restrict__ inst) {
    __shared__ int   s_int[32*16*4];             // 8KB: one write per (warp,id), no atomics
    __shared__ float s_flt[32*16*10];            // 20KB: [warp][id][slot(2)][stat(4)+pad]
    int tid = threadIdx.x;
    int lane = tid & 31, wid = tid >> 5;
    for (int i = tid; i < 32*16*4; i += 1024) s_int[i] = 0;
    for (int i = tid; i < 32*16*10; i += 1024) s_flt[i] = 0.f;
    __syncthreads();

    const int bpb = DHW/1024;                    // 1152 blocks per batch (exact)
    int b = blockIdx.x / bpb;
    int v = (blockIdx.x % bpb)*1024 + tid;

    int warpbase = v & ~31;
    int w0 = warpbase % WW;                      // warp-uniform
    int t2 = warpbase / WW;
    int hi = t2 % HH;                            // warp-uniform
    int di = t2 / HH;                            // warp-uniform

    size_t pbase = (size_t)b*CCH*DHW + v;
    float s0 = pred[pbase + 3*(size_t)DHW];
    float s1 = pred[pbase + 4*(size_t)DHW];
    float s2 = pred[pbase + 5*(size_t)DHW];
    int iv = inst[(size_t)b*DHW + v];

    // one ballot per id; lane i keeps mask for id i
    unsigned mymask = 0;
    #pragma unroll
    for (int id = 0; id < NIDS; id++) {
        unsigned m = __ballot_sync(0xffffffffu, iv == id+1);
        if (lane == id) mymask = m;
    }
    if (lane < NIDS && mymask) {
        int cnt = __popc(mymask);
        int sl  = __popc(mymask & 0xFFFF0000u)*16
                + __popc(mymask & 0xFF00FF00u)*8
                + __popc(mymask & 0xF0F0F0F0u)*4
                + __popc(mymask & 0xCCCCCCCCu)*2
                + __popc(mymask & 0xAAAAAAAAu);   // sum of set lane indices
        int* si = &s_int[(wid*16 + lane)*4];
        si[0] = cnt;
        si[1] = w0*cnt + sl;                     // sum wi
        si[2] = hi*cnt;                          // sum hi
        si[3] = di*cnt;                          // sum di
    }
    if (iv >= 1 && iv <= NIDS) {
        float* a = &s_flt[(wid*16 + (iv-1))*10 + (lane & 1)*5];
        atomicAdd(&a[0], s0);
        atomicAdd(&a[1], s1);
        atomicAdd(&a[2], s2);
        atomicAdd(&a[3], s0*s0 + s1*s1 + s2*s2);
    }
    __syncthreads();

    // flush: 128 threads = 16 ids x 8 stats (0=cnt,1=Sx,2=Sy,3=Sz,4..6=Ss,7=Sq)
    if (tid < 128) {
        int id = tid >> 3, k = tid & 7;
        double val = 0.0;
        if (k < 4) {
            long long acc = 0;
            #pragma unroll
            for (int w = 0; w < 32; w++) acc += (long long)s_int[(w*16 + id)*4 + k];
            if      (k == 0) val = (double)acc;
            else if (k == 3) val = (double)acc * (1.0/31.0);
            else             val = (double)acc * (1.0/191.0);
        } else {
            float f = 0.f;
            #pragma unroll
            for (int w = 0; w < 32; w++) {
                const float* a = &s_flt[(w*16 + id)*10];
                f += a[k-4] + a[5 + (k-4)];
            }
            val = (double)f;
        }
        if (val != 0.0) atomicAdd(&g_stats[b*NIDS + id][k], val);
    }
}

// ---------------- K2: finalize per-instance params (+ self-zero stats) ----------------
__global__ void finalize_stats_kernel() {
    int i = threadIdx.x;
    if (i >= NSEG) return;
    double s[8];
    #pragma unroll
    for (int k = 0; k < 8; k++) { s[k] = g_stats[i][k]; g_stats[i][k] = 0.0; }
    double cnt  = s[0];
    double safe = cnt > 1.0 ? cnt : 1.0;
    double inv  = 1.0/safe;
    double c0 = s[1]*inv, c1 = s[2]*inv, c2 = s[3]*inv;
    double m0 = s[4]*inv, m1 = s[5]*inv, m2 = s[6]*inv;
    double varnum = s[7] - 2.0*(m0*s[4] + m1*s[5] + m2*s[6])
                  + (m0*m0 + m1*m1 + m2*m2)*cnt;
    double var = varnum/(3.0*safe);
    g_params[i][0] = (float)c0;
    g_params[i][1] = (float)c1;
    g_params[i][2] = (float)c2;
    g_params[i][3] = expf(10.f*(float)m0);
    g_params[i][4] = expf(10.f*(float)m1);
    g_params[i][5] = expf(10.f*(float)m2);
    g_params[i][6] = (float)cnt;
    g_params[i][7] = (float)var;
}

// ---------------- K3: fused preprocess + dist + histogram + seed losses ----------------
__global__ __launch_bounds__(256) void hist_kernel(const float* __restrict__ pred,
                                                   const int* __restrict__ inst,
                                                   const int* __restrict__ lab) {
    __shared__ float s_p[NIDS*6];
    __shared__ float s_sl[NIDS];
    __shared__ float s_bg;
    int tid = threadIdx.x;
    int lane = tid & 31;
    const int bpb = DHW/256;
    int b = blockIdx.x / bpb;
    int v = (blockIdx.x % bpb)*256 + tid;
    if (tid < NIDS*6) s_p[tid] = g_params[b*NIDS + tid/6][tid%6];
    if (tid < NIDS) s_sl[tid] = 0.f;
    if (tid == 0) s_bg = 0.f;
    __syncthreads();

    int wi = v % WW;
    int t2 = v / WW;
    int hh = t2 % HH;
    int dd = t2 / HH;
    float x0 = (float)wi * (1.f/191.f);
    float x1 = (float)hh * (1.f/191.f);
    float x2 = (float)dd * (1.f/31.f);

    size_t pbase = (size_t)b*CCH*DHW + v;
    float p0 = pred[pbase];
    float p1 = pred[pbase + (size_t)DHW];
    float p2 = pred[pbase + 2*(size_t)DHW];
    float p6 = pred[pbase + 6*(size_t)DHW];
    int iv   = inst[(size_t)b*DHW + v];
    int lv   = lab[(size_t)b*DHW + v];

    float se0 = tanhf(p0) + x0;
    float se1 = tanhf(p1) + x1;
    float se2 = tanhf(p2) + x2;
    float sd  = 1.f/(1.f + __expf(-p6));

    // bg seed: warp reduce then one shared atomic per warp
    float bgv = (lv == 0) ? sd*sd : 0.f;
    #pragma unroll
    for (int off = 16; off; off >>= 1) bgv += __shfl_down_sync(0xffffffffu, bgv, off);
    if (lane == 0 && bgv != 0.f) atomicAdd(&s_bg, bgv);

    u64* hb = g_hist + (((size_t)b*NIDS) << NBITS);
    #pragma unroll
    for (int i = 0; i < NIDS; i++) {
        float d0 = se0 - s_p[i*6+0];
        float d1 = se1 - s_p[i*6+1];
        float d2 = se2 - s_p[i*6+2];
        float q  = d0*d0*s_p[i*6+3] + d1*d1*s_p[i*6+4] + d2*d2*s_p[i*6+5];
        float d  = __expf(-q);
        bool gt  = (iv == i+1);
        float e  = gt ? (2.f - 2.f*d) : (2.f*d);
        int bin  = (int)(e * (float)(NB/2));
        if (bin > NB-1) bin = NB-1;
        if (bin < 0) bin = 0;
        atomicAdd(&hb[((size_t)i << NBITS) + bin], gt ? (1ULL<<32) : 1ULL);
        if (gt) { float df = sd - d; atomicAdd(&s_sl[i], df*df); }
    }
    __syncthreads();
    if (tid < NIDS && s_sl[tid] != 0.f)
        atomicAdd(&g_seedl[b*NIDS + tid], (double)s_sl[tid]);
    if (tid == 0 && s_bg != 0.f) atomicAdd(&g_bg[b], (double)s_bg);
}

// ---------------- K4a: per-chunk packed sums (coalesced, chip-filling grid) ----------------
__global__ __launch_bounds__(256) void chunk_sum_kernel() {
    int lane = threadIdx.x & 31;
    int gw = blockIdx.x*8 + (threadIdx.x >> 5);  // global warp id, 4096 total
    int seg = gw >> 6;
    int ch  = gw & (NCH-1);
    const u64* hist = g_hist + ((size_t)seg << NBITS);
    int base = ch*CHUNK;                         // descending-position base
    u64 sum = 0;
    #pragma unroll 8
    for (int r = 0; r < ROUNDS; r++) {
        u64 hv = hist[NB-1 - (base + r*32 + lane)];
        sum += hv + (hv >> 32);
    }
    #pragma unroll
    for (int off = 16; off; off >>= 1)
        sum += __shfl_down_sync(0xffffffffu, sum, off);
    if (lane == 0) g_csum[seg][ch] = sum;
}

// ---------------- K4b: Lovasz main pass (coalesced, self-zeroes hist) ----------------
__global__ __launch_bounds__(256) void lovasz_scan_kernel() {
    int lane = threadIdx.x & 31;
    int gw = blockIdx.x*8 + (threadIdx.x >> 5);
    int seg = gw >> 6;
    int ch  = gw & (NCH-1);
    u64* hist = g_hist + ((size_t)seg << NBITS);
    long long gts = (long long)(g_params[seg][6] + 0.5f);

    // inter-chunk exclusive prefix: sum csum of chunks [0, ch)
    u64 pre = 0;
    if (lane < ch) pre = g_csum[seg][lane];
    if (lane + 32 < ch) pre += g_csum[seg][lane + 32];
    #pragma unroll
    for (int off = 16; off; off >>= 1)
        pre += __shfl_xor_sync(0xffffffffu, pre, off);
    u64 carry = pre;                             // same in all lanes

    int base = ch*CHUNK;
    double acc = 0.0;
    const float width = 2.0f / (float)NB;

    #pragma unroll 4
    for (int r = 0; r < ROUNDS; r++) {
        int bin = NB-1 - (base + r*32 + lane);
        u64 hv = hist[bin];
        hist[bin] = 0ULL;                        // self-clean for next replay
        u64 pack = hv + (hv >> 32);

        // inclusive warp scan (ascending lane = descending bin order)
        u64 x = pack;
        #pragma unroll
        for (int off = 1; off < 32; off <<= 1) {
            u64 y = __shfl_up_sync(0xffffffffu, x, off);
            if (lane >= off) x += y;
        }
        u64 tot = __shfl_sync(0xffffffffu, x, 31);
        u64 run = carry + x - pack;              // exclusive prefix for this bin
        carry += tot;

        unsigned n1 = (unsigned)(hv >> 32);
        unsigned n0 = (unsigned)hv;
        if (n1 + n0) {
            long long n1b = (long long)(run >> 32);     // gt before this bin
            long long ntb = (long long)(unsigned)run;   // total before this bin
            long long interb = gts - n1b;
            long long unionb = gts + (ntb - n1b);
            long long intere = interb - (long long)n1;
            long long unione = unionb + (long long)n0;
            // Je - Jb = interb/unionb - intere/unione (exact int64 cross product)
            long long num = interb*unione - intere*unionb;
            long long den = unionb*unione;
            float e_rep = ((float)bin + 0.5f) * width;
            acc += (double)e_rep * ((double)num / (double)den);
        }
    }

    #pragma unroll
    for (int off = 16; off; off >>= 1)
        acc += __shfl_down_sync(0xffffffffu, acc, off);
    if (lane == 0 && gts > 0 && acc != 0.0)
        atomicAdd(&g_instl[seg], acc);
}

// ---------------- K5: final combine (+ self-zero accumulators) ----------------
__global__ void final_kernel(float* __restrict__ out) {
    if (threadIdx.x != 0) return;
    float li = 0.f, lv = 0.f, ls = 0.f;
    for (int b = 0; b < BATCH; b++) {
        float obj = 0.f, vb = 0.f, ib = 0.f, sb = 0.f;
        for (int i = 0; i < NIDS; i++) {
            int s = b*NIDS + i;
            float cnt = g_params[s][6];
            if (cnt > 0.f) {
                obj += 1.f;
                vb += g_params[s][7];
                ib += (float)g_instl[s];
                sb += (float)g_seedl[s];
            }
            g_seedl[s] = 0.0;
            g_instl[s] = 0.0;
        }
        float denom = obj > 1.f ? obj : 1.f;
        li += ib/denom;
        lv += vb/denom;
        ls += (sb + (float)g_bg[b]) / (float)DHW;
        g_bg[b] = 0.0;
    }
    li = li * 1.0f / BATCH;          // W_INST
    lv = lv * 10.0f / BATCH;         // W_VAR
    ls = ls * 1.0f / BATCH;          // W_SEED
    out[0] = li; out[1] = lv; out[2] = ls; out[3] = li + lv + ls;
}

// ---------------- launch ----------------
extern "C" void kernel_launch(void* const* d_in, const int* in_sizes, int n_in,
                              void* d_out, int out_size) {
    const float* pred = (const float*)d_in[0];
    const int*   inst = (const int*)d_in[1];
    const int*   lab  = (const int*)d_in[2];
    // d_in[3] = center_images (unused), d_in[4] = xyzm (grid; computed inline)
    float* out = (float*)d_out;

    stats_kernel<<<BATCH*(DHW/1024), 1024>>>(pred, inst);
    finalize_stats_kernel<<<1, 64>>>();
    hist_kernel<<<BATCH*(DHW/256), 256>>>(pred, inst, lab);
    chunk_sum_kernel<<<(NSEG*NCH)/8, 256>>>();
    lovasz_scan_kernel<<<(NSEG*NCH)/8, 256>>>();
    final_kernel<<<1, 32>>>(out);
}